// round 8
// baseline (speedup 1.0000x reference)
#include <cuda_runtime.h>
#include <cstdint>
#include <stdint.h>
#include <math.h>

#define HDIM   64
#define CNEI   32
#define NBLK   8
#define NTHR   1024
#define TROWS  32
#define NROWS  48
#define WPACK  1128
#define EN_BYTES   32
#define EN_EXPECT  ((NBLK - 1) * EN_BYTES)
#define VEC_BYTES  256

__device__ __forceinline__ float gelu_exact(float v) {
    return 0.5f * v * (1.0f + erff(v * 0.70710678118654752440f));
}
__device__ __forceinline__ uint32_t mapa_u32(uint32_t addr, uint32_t rank) {
    uint32_t d;
    asm("mapa.shared::cluster.u32 %0, %1, %2;" : "=r"(d) : "r"(addr), "r"(rank));
    return d;
}
__device__ __forceinline__ void cluster_sync_all() {
    asm volatile("barrier.cluster.arrive.aligned;" ::: "memory");
    asm volatile("barrier.cluster.wait.aligned;"   ::: "memory");
}
__device__ __forceinline__ void mbar_init(uint32_t a, uint32_t cnt) {
    asm volatile("mbarrier.init.shared.b64 [%0], %1;" :: "r"(a), "r"(cnt) : "memory");
}
__device__ __forceinline__ void mbar_arrive_expect(uint32_t a, uint32_t tx) {
    asm volatile("mbarrier.arrive.expect_tx.shared.b64 _, [%0], %1;" :: "r"(a), "r"(tx) : "memory");
}
__device__ __forceinline__ void mbar_wait(uint32_t a, uint32_t parity) {
    uint32_t done;
    asm volatile(
        "{\n\t.reg .pred p;\n\t"
        "mbarrier.try_wait.parity.acquire.cta.shared::cta.b64 p, [%1], %2;\n\t"
        "selp.b32 %0, 1, 0, p;\n\t}"
        : "=r"(done) : "r"(a), "r"(parity) : "memory");
    if (!done) {
        asm volatile(
            "{\n\t.reg .pred P1;\n\t"
            "WAIT_LOOP_%=:\n\t"
            "mbarrier.try_wait.parity.acquire.cta.shared::cta.b64 P1, [%0], %1, 0x989680;\n\t"
            "@P1 bra.uni WAIT_DONE_%=;\n\t"
            "bra.uni WAIT_LOOP_%=;\n\t"
            "WAIT_DONE_%=:\n\t}"
            :: "r"(a), "r"(parity) : "memory");
    }
}
__device__ __forceinline__ void bulk_s2s(uint32_t dst, uint32_t src, uint32_t bytes, uint32_t rmbar) {
    asm volatile(
        "cp.async.bulk.shared::cluster.shared::cta.mbarrier::complete_tx::bytes [%0], [%1], %2, [%3];"
        :: "r"(dst), "r"(src), "r"(bytes), "r"(rmbar) : "memory");
}

__global__ __launch_bounds__(NTHR, 1) __cluster_dims__(NBLK, 1, 1)
void bralm_kernel(const float* __restrict__ W,
                  const float* __restrict__ Bb,
                  const float* __restrict__ POS,
                  const int*   __restrict__ SE,
                  const int*   __restrict__ NE,
                  const int*   __restrict__ NN,
                  const int*   __restrict__ X0P,
                  const int*   __restrict__ MNTP,
                  float* __restrict__ out,
                  int out_size, int L)
{
    __shared__ float pe_s[TROWS][HDIM];               // 8 KB
    __shared__ float cache_s[NROWS][HDIM];            // 12 KB
    __shared__ float wts_p[WPACK];                    // 4.5 KB
    __shared__ float red_s[8][HDIM];                  // 2 KB
    __shared__ float red_f[4][8][HDIM];               // 8 KB
    __shared__ __align__(16) float vec_loc[2][4][HDIM];  // 2 KB
    __shared__ __align__(16) float win_vec[2][HDIM];     // 0.5 KB
    __shared__ __align__(32) float en_rx[2][NBLK][8];    // 0.5 KB
    __shared__ float pos_s[64];
    __shared__ float dt_s[32];
    __shared__ int   tok_s[TROWS];
    __shared__ int   ne_br[CNEI][4];
    __shared__ int   edge0[4];
    __shared__ int   x_sh;
    __shared__ __align__(8) unsigned long long mbarE[2], mbarV[2];

    const int tid  = threadIdx.x;
    const int lane = tid & 31;
    uint32_t myrank;
    asm("mov.u32 %0, %%cluster_ctarank;" : "=r"(myrank));

    const uint32_t mbE_a[2] = { (uint32_t)__cvta_generic_to_shared(&mbarE[0]),
                                (uint32_t)__cvta_generic_to_shared(&mbarE[1]) };
    const uint32_t mbV_a[2] = { (uint32_t)__cvta_generic_to_shared(&mbarV[0]),
                                (uint32_t)__cvta_generic_to_shared(&mbarV[1]) };

    int T = (MNTP != nullptr) ? MNTP[0] : 32;
    if (T < 0) T = 0;
    if (L + T > NROWS) T = NROWS - L;
    if (T > TROWS)     T = TROWS;

    // ---------------- init ----------------
    if (tid == 0) {
        mbar_init(mbE_a[0], 1); mbar_init(mbE_a[1], 1);
        mbar_init(mbV_a[0], 1); mbar_init(mbV_a[1], 1);
    }
    if (tid < HDIM / 2)
        dt_s[tid] = (float)pow(10000.0, (double)(2 * tid) / 64.0);
    for (int i = tid; i < NROWS * HDIM; i += NTHR)
        cache_s[i >> 6][i & 63] = 0.0f;
    if (tid < 64) pos_s[tid] = POS[tid];
    __syncthreads();

    for (int idx = tid; idx < TROWS * HDIM; idx += NTHR) {
        int i = idx >> 6, h = idx & 63;
        float argf = (float)i * dt_s[h >> 1];
        double ad = (double)argf;
        double kq2 = rint(ad * 0.15915494309189535);
        double r   = fma(-kq2, 6.283185307179586, ad);
        pe_s[i][h] = (h & 1) ? cosf((float)r) : sinf((float)r);
    }
    {   // packed triangular softmax table, rows c = 1..47
        int w = tid >> 5;
        for (int c = w + 1; c < NROWS; c += 32) {
            float v0 = (lane      < c) ? pos_s[lane]      : -INFINITY;
            float v1 = (lane + 32 < c) ? pos_s[lane + 32] : -INFINITY;
            float m = fmaxf(v0, v1);
            #pragma unroll
            for (int off = 16; off > 0; off >>= 1)
                m = fmaxf(m, __shfl_xor_sync(0xffffffffu, m, off));
            float u0 = (lane      < c) ? expf(v0 - m) : 0.0f;
            float u1 = (lane + 32 < c) ? expf(v1 - m) : 0.0f;
            float s = u0 + u1;
            #pragma unroll
            for (int off = 16; off > 0; off >>= 1)
                s += __shfl_xor_sync(0xffffffffu, s, off);
            int base = c * (c - 1) / 2;
            if (lane      < c) wts_p[base + lane]      = u0 / s;
            if (lane + 32 < c) wts_p[base + lane + 32] = u1 / s;
        }
    }
    __syncthreads();

    // thread roles
    const int g   = tid >> 8;        // group / candidate 0..3
    const int tc  = tid & 255;
    const int hp  = tc >> 4;         // 0..15 -> 4 rows each... (rows hp*4..hp*4+3)
    const int kq  = tc & 15;         // float4 column quad
    const int w2  = tc >> 5;         // warp within group 0..7

    // ---------------- prompt: 4-group weight rotation ----------------
    float4 wvp[4];
    if (g < L) {
        int e0 = SE[g];
        const float4* Wb = (const float4*)(W + (size_t)e0 * (HDIM * HDIM));
        #pragma unroll
        for (int r = 0; r < 4; ++r) wvp[r] = Wb[(hp * 4 + r) * 16 + kq];
    }
    float bias_cur = 0.0f, bias_nxt = 0.0f;
    if (tid < 64 && L > 0) bias_cur = Bb[(size_t)SE[0] * HDIM + tid];

    for (int i = 0; i < L; ++i) {
        int grp = i & 3;
        if (tid < 64 && i + 1 < L) bias_nxt = Bb[(size_t)SE[i + 1] * HDIM + tid];

        if (g == grp) {
            float e4[4];
            if (i == 0) {
                #pragma unroll
                for (int r = 0; r < 4; ++r) e4[r] = 1.0f / 64.0f;
            } else {
                int base = i * (i - 1) / 2;
                float4 acc = make_float4(0.f, 0.f, 0.f, 0.f);
                for (int j = 0; j < i; ++j) {
                    float wj = wts_p[base + j];
                    float4 cj = *(const float4*)&cache_s[j][hp * 4];
                    acc.x = fmaf(wj, cj.x, acc.x); acc.y = fmaf(wj, cj.y, acc.y);
                    acc.z = fmaf(wj, cj.z, acc.z); acc.w = fmaf(wj, cj.w, acc.w);
                }
                e4[0] = acc.x; e4[1] = acc.y; e4[2] = acc.z; e4[3] = acc.w;
            }
            float4 a4 = make_float4(0.f, 0.f, 0.f, 0.f);
            #pragma unroll
            for (int r = 0; r < 4; ++r) {
                float ev = e4[r];
                a4.x = fmaf(ev, wvp[r].x, a4.x); a4.y = fmaf(ev, wvp[r].y, a4.y);
                a4.z = fmaf(ev, wvp[r].z, a4.z); a4.w = fmaf(ev, wvp[r].w, a4.w);
            }
            a4.x += __shfl_xor_sync(0xffffffffu, a4.x, 16);
            a4.y += __shfl_xor_sync(0xffffffffu, a4.y, 16);
            a4.z += __shfl_xor_sync(0xffffffffu, a4.z, 16);
            a4.w += __shfl_xor_sync(0xffffffffu, a4.w, 16);
            if ((tc & 16) == 0)
                *(float4*)&red_f[0][w2][kq * 4] = a4;
            // prefetch this group's next weights (step i+4)
            int ni = i + 4;
            if (ni < L) {
                int en = SE[ni];
                const float4* Wb = (const float4*)(W + (size_t)en * (HDIM * HDIM));
                #pragma unroll
                for (int r = 0; r < 4; ++r) wvp[r] = Wb[(hp * 4 + r) * 16 + kq];
            }
        }
        __syncthreads();
        if (tid < 64) {
            float v = 0.0f;
            #pragma unroll
            for (int q = 0; q < 8; ++q) v += red_f[0][q][tid];
            v += bias_cur + pe_s[i][tid];
            cache_s[i][tid] = gelu_exact(v);
            bias_cur = bias_nxt;
        }
        __syncthreads();
    }

    // ---------------- generation priming ----------------
    if (tid == 0) x_sh = (X0P != nullptr) ? X0P[0] : 7;
    __syncthreads();
    const int x0v = x_sh;

    int nn_reg = 0, nn_next = 0;
    if (tid < 32) {
        nn_reg = NN[(size_t)x0v * CNEI + tid];
        #pragma unroll
        for (int c = 0; c < 4; ++c)
            ne_br[tid][c] = NE[(size_t)nn_reg * CNEI + myrank * 4 + c];
    }
    if (tid < 4) edge0[tid] = NE[(size_t)x0v * CNEI + myrank * 4 + tid];
    __syncthreads();

    float4 wv[4];
    {
        const float4* Wb = (const float4*)(W + (size_t)edge0[g] * (HDIM * HDIM));
        #pragma unroll
        for (int r = 0; r < 4; ++r) wv[r] = Wb[(hp * 4 + r) * 16 + kq];
    }
    float bias_r = 0.0f;
    if (tid < 256) bias_r = Bb[(size_t)edge0[tid >> 6] * HDIM + (tid & 63)];

    float e_r[4];
    if (T > 0) {
        int base = L * (L - 1) / 2;
        if (tid >= 512) {
            int p = (tid >> 6) - 8, k = tid & 63;
            float acc = 0.0f;
            for (int j = p; j < L; j += 8)
                acc = fmaf(wts_p[base + j], cache_s[j][k], acc);
            red_s[p][k] = acc;
        }
        __syncthreads();
        {
            float4 acc = make_float4(0.f, 0.f, 0.f, 0.f);
            #pragma unroll
            for (int q = 0; q < 8; ++q) {
                float4 rq = *(const float4*)&red_s[q][hp * 4];
                acc.x += rq.x; acc.y += rq.y; acc.z += rq.z; acc.w += rq.w;
            }
            e_r[0] = acc.x; e_r[1] = acc.y; e_r[2] = acc.z; e_r[3] = acc.w;
        }
    }
    // all CTAs: mbarriers init'd before any push can arrive
    cluster_sync_all();
    __syncthreads();

    // ---------------- generation loop ----------------
    for (int t = 0; t < T; ++t) {
        const int curr = L + t;
        const int cb   = t & 1;
        const uint32_t par = (uint32_t)((t >> 1) & 1);

        if (tid == 0) {
            mbar_arrive_expect(mbE_a[cb], EN_EXPECT);
            mbar_arrive_expect(mbV_a[cb], VEC_BYTES);
        }

        // 1) matvec partials (register e, preloaded weights)
        {
            float4 a4 = make_float4(0.f, 0.f, 0.f, 0.f);
            #pragma unroll
            for (int r = 0; r < 4; ++r) {
                float ev = e_r[r];
                a4.x = fmaf(ev, wv[r].x, a4.x); a4.y = fmaf(ev, wv[r].y, a4.y);
                a4.z = fmaf(ev, wv[r].z, a4.z); a4.w = fmaf(ev, wv[r].w, a4.w);
            }
            a4.x += __shfl_xor_sync(0xffffffffu, a4.x, 16);
            a4.y += __shfl_xor_sync(0xffffffffu, a4.y, 16);
            a4.z += __shfl_xor_sync(0xffffffffu, a4.z, 16);
            a4.w += __shfl_xor_sync(0xffffffffu, a4.w, 16);
            if ((tc & 16) == 0)
                *(float4*)&red_f[g][w2][kq * 4] = a4;
        }
        __syncthreads();   // bar1

        // 2) combine+gelu+local energy | NE branch gathers | pooled partials
        if (tid < 256) {
            if (tid < 32 && t > 0) {
                nn_reg = nn_next;
                int e0 = NE[(size_t)nn_reg * CNEI + myrank * 4 + 0];
                int e1 = NE[(size_t)nn_reg * CNEI + myrank * 4 + 1];
                int e2 = NE[(size_t)nn_reg * CNEI + myrank * 4 + 2];
                int e3 = NE[(size_t)nn_reg * CNEI + myrank * 4 + 3];
                ne_br[lane][0] = e0; ne_br[lane][1] = e1;
                ne_br[lane][2] = e2; ne_br[lane][3] = e3;
            }
            int cand = tid >> 6, kk = tid & 63;
            float v = 0.0f;
            #pragma unroll
            for (int q = 0; q < 8; ++q) v += red_f[cand][q][kk];
            v += bias_r + pe_s[t][kk];
            float ge = gelu_exact(v);
            vec_loc[cb][cand][kk] = ge;
            float sq = ge * ge;
            #pragma unroll
            for (int off = 16; off > 0; off >>= 1)
                sq += __shfl_xor_sync(0xffffffffu, sq, off);
            if (lane == 0) en_rx[cb][myrank][tid >> 5] = sq;
        } else if (tid >= 512 && t + 1 < T) {
            int p = (tid >> 6) - 8, k = tid & 63;
            int base1 = (curr + 1) * curr / 2;
            float acc = 0.0f;
            for (int j = p; j < curr; j += 8)
                acc = fmaf(wts_p[base1 + j], cache_s[j][k], acc);
            red_s[p][k] = acc;
        }
        __syncthreads();   // bar2

        // 3) push energies (32 B) to 7 peers
        if (tid == 0) {
            asm volatile("fence.proxy.async.shared::cta;" ::: "memory");
            uint32_t esrc = (uint32_t)__cvta_generic_to_shared(&en_rx[cb][myrank][0]);
            #pragma unroll
            for (int r = 0; r < NBLK; ++r) {
                if ((uint32_t)r == myrank) continue;
                bulk_s2s(mapa_u32(esrc, (uint32_t)r), esrc, EN_BYTES, mapa_u32(mbE_a[cb], (uint32_t)r));
            }
        }
        mbar_wait(mbE_a[cb], par);

        // 4) redundant per-warp argmax on raw sum-of-squares
        int bi;
        {
            int rr = lane >> 2, cl = lane & 3;
            float2 eh = *(const float2*)&en_rx[cb][rr][cl * 2];
            float best = eh.x + eh.y;
            bi = lane;
            #pragma unroll
            for (int off = 16; off > 0; off >>= 1) {
                float bo = __shfl_xor_sync(0xffffffffu, best, off);
                int   io = __shfl_xor_sync(0xffffffffu, bi, off);
                if (bo > best || (bo == best && io < bi)) { best = bo; bi = io; }
            }
        }

        // 5) winner pushes its 256 B vector to all ranks (incl. self)
        if (tid == 0 && (bi >> 2) == (int)myrank) {
            uint32_t vsrc = (uint32_t)__cvta_generic_to_shared(&vec_loc[cb][bi & 3][0]);
            uint32_t wdst = (uint32_t)__cvta_generic_to_shared(&win_vec[cb][0]);
            #pragma unroll
            for (int r = 0; r < NBLK; ++r)
                bulk_s2s(mapa_u32(wdst, (uint32_t)r), vsrc, VEC_BYTES, mapa_u32(mbV_a[cb], (uint32_t)r));
        }

        // 6) next-step weight/bias loads (overlap vector transfer)
        {
            int edge_g = ne_br[bi][g];
            const float4* Wb = (const float4*)(W + (size_t)edge_g * (HDIM * HDIM));
            #pragma unroll
            for (int r = 0; r < 4; ++r) wv[r] = Wb[(hp * 4 + r) * 16 + kq];
        }
        if (tid < 256)
            bias_r = Bb[(size_t)ne_br[bi][tid >> 6] * HDIM + (tid & 63)];
        if (tid < 32) {
            int y = __shfl_sync(0xffffffffu, nn_reg, bi);
            if (lane == 0) tok_s[t] = y;
            nn_next = NN[(size_t)y * CNEI + lane];
        }

        mbar_wait(mbV_a[cb], par);

        // 7) cache row + in-register e update (no barrier needed)
        if (tid < 64) cache_s[curr][tid] = win_vec[cb][tid];
        if (t + 1 < T) {
            float wcur = wts_p[(curr + 1) * curr / 2 + curr];
            float4 acc = make_float4(0.f, 0.f, 0.f, 0.f);
            #pragma unroll
            for (int q = 0; q < 8; ++q) {
                float4 rq = *(const float4*)&red_s[q][hp * 4];
                acc.x += rq.x; acc.y += rq.y; acc.z += rq.z; acc.w += rq.w;
            }
            float4 wn = *(const float4*)&win_vec[cb][hp * 4];
            e_r[0] = fmaf(wcur, wn.x, acc.x);
            e_r[1] = fmaf(wcur, wn.y, acc.y);
            e_r[2] = fmaf(wcur, wn.z, acc.z);
            e_r[3] = fmaf(wcur, wn.w, acc.w);
        }
    }

    // ensure outgoing bulk reads of our smem have drained before exit
    cluster_sync_all();
    __syncthreads();

    // ---------------- output (CTA 0) ----------------
    if (blockIdx.x == 0) {
        int ncache = (L + T) * HDIM;
        for (int i = tid; i < out_size; i += NTHR) {
            float v;
            if (i < ncache) v = cache_s[i >> 6][i & 63];
            else {
                int tt = i - ncache;
                v = (tt < T) ? (float)tok_s[tt] : 0.0f;
            }
            out[i] = v;
        }
    }
}

extern "C" void kernel_launch(void* const* d_in, const int* in_sizes, int n_in,
                              void* d_out, int out_size) {
    const float* W   = (const float*)d_in[0];
    const float* B   = (const float*)d_in[1];
    const float* POS = (const float*)d_in[2];
    const int*   SE  = (const int*)d_in[3];
    const int*   NE  = (const int*)d_in[4];
    const int*   NN  = (const int*)d_in[5];
    const int*   X0  = (n_in > 6) ? (const int*)d_in[6] : nullptr;
    const int*   MNT = (n_in > 7) ? (const int*)d_in[7] : nullptr;
    int L = in_sizes[3];

    bralm_kernel<<<NBLK, NTHR>>>(W, B, POS, SE, NE, NN, X0, MNT,
                                 (float*)d_out, out_size, L);
}

// round 9
// speedup vs baseline: 1.0832x; 1.0832x over previous
#include <cuda_runtime.h>
#include <cstdint>
#include <stdint.h>
#include <math.h>

#define HDIM   64
#define CNEI   32
#define NBLK   8
#define NTHR   1024
#define TROWS  32
#define NROWS  48
#define WPACK  1128

struct __align__(16) PushBlk { float vec[4][HDIM]; float en[8]; };  // 1056 B
#define PUSH_BYTES 1056
#define EXPECT_TX ((NBLK - 1) * PUSH_BYTES)

struct __align__(16) Smem {
    PushBlk rx[2][NBLK];              // 16896 B
    float pe[TROWS][HDIM];            // 8 KB
    float cache[NROWS][HDIM];         // 12 KB
    float wts[WPACK];                 // 4.5 KB
    float red_s[8][HDIM];             // 2 KB
    float red_f[4][8][HDIM];          // 8 KB
    float pos[64];
    float dt[32];
    int   tok[TROWS];
    int   ne_br[CNEI][4];
    int   edge0[4];
    int   x0;
    unsigned long long mbar[2];
};

__device__ __forceinline__ float gelu_exact(float v) {
    return 0.5f * v * (1.0f + erff(v * 0.70710678118654752440f));
}
__device__ __forceinline__ uint32_t mapa_u32(uint32_t addr, uint32_t rank) {
    uint32_t d;
    asm("mapa.shared::cluster.u32 %0, %1, %2;" : "=r"(d) : "r"(addr), "r"(rank));
    return d;
}
__device__ __forceinline__ void cluster_sync_all() {
    asm volatile("barrier.cluster.arrive.aligned;" ::: "memory");
    asm volatile("barrier.cluster.wait.aligned;"   ::: "memory");
}
__device__ __forceinline__ void mbar_init(uint32_t a, uint32_t cnt) {
    asm volatile("mbarrier.init.shared.b64 [%0], %1;" :: "r"(a), "r"(cnt) : "memory");
}
__device__ __forceinline__ void mbar_arrive_expect(uint32_t a, uint32_t tx) {
    asm volatile("mbarrier.arrive.expect_tx.shared.b64 _, [%0], %1;" :: "r"(a), "r"(tx) : "memory");
}
__device__ __forceinline__ void mbar_wait(uint32_t a, uint32_t parity) {
    uint32_t done;
    asm volatile(
        "{\n\t.reg .pred p;\n\t"
        "mbarrier.try_wait.parity.acquire.cta.shared::cta.b64 p, [%1], %2;\n\t"
        "selp.b32 %0, 1, 0, p;\n\t}"
        : "=r"(done) : "r"(a), "r"(parity) : "memory");
    if (!done) {
        asm volatile(
            "{\n\t.reg .pred P1;\n\t"
            "WAIT_LOOP_%=:\n\t"
            "mbarrier.try_wait.parity.acquire.cta.shared::cta.b64 P1, [%0], %1, 0x989680;\n\t"
            "@P1 bra.uni WAIT_DONE_%=;\n\t"
            "bra.uni WAIT_LOOP_%=;\n\t"
            "WAIT_DONE_%=:\n\t}"
            :: "r"(a), "r"(parity) : "memory");
    }
}
__device__ __forceinline__ void bulk_s2s(uint32_t dst, uint32_t src, uint32_t bytes, uint32_t rmbar) {
    asm volatile(
        "cp.async.bulk.shared::cluster.shared::cta.mbarrier::complete_tx::bytes [%0], [%1], %2, [%3];"
        :: "r"(dst), "r"(src), "r"(bytes), "r"(rmbar) : "memory");
}

__global__ __launch_bounds__(NTHR, 1) __cluster_dims__(NBLK, 1, 1)
void bralm_kernel(const float* __restrict__ W,
                  const float* __restrict__ Bb,
                  const float* __restrict__ POS,
                  const int*   __restrict__ SE,
                  const int*   __restrict__ NE,
                  const int*   __restrict__ NN,
                  const int*   __restrict__ X0P,
                  const int*   __restrict__ MNTP,
                  float* __restrict__ out,
                  int out_size, int L)
{
    extern __shared__ __align__(16) char smem_raw[];
    Smem* S = (Smem*)smem_raw;
    __shared__ float e_vec[HDIM];   // prompt-phase e only

    const int tid  = threadIdx.x;
    const int lane = tid & 31;
    uint32_t myrank;
    asm("mov.u32 %0, %%cluster_ctarank;" : "=r"(myrank));

    const uint32_t mbar_a0 = (uint32_t)__cvta_generic_to_shared(&S->mbar[0]);
    const uint32_t mbar_a1 = (uint32_t)__cvta_generic_to_shared(&S->mbar[1]);

    int T = (MNTP != nullptr) ? MNTP[0] : 32;
    if (T < 0) T = 0;
    if (L + T > NROWS) T = NROWS - L;
    if (T > TROWS)     T = TROWS;

    // ---------------- init ----------------
    if (tid == 0) { mbar_init(mbar_a0, 1); mbar_init(mbar_a1, 1); }
    if (tid < HDIM / 2)
        S->dt[tid] = (float)pow(10000.0, (double)(2 * tid) / 64.0);
    for (int i = tid; i < NROWS * HDIM; i += NTHR)
        S->cache[i >> 6][i & 63] = 0.0f;
    if (tid < 64) S->pos[tid] = POS[tid];
    __syncthreads();

    for (int idx = tid; idx < TROWS * HDIM; idx += NTHR) {
        int i = idx >> 6, h = idx & 63;
        float argf = (float)i * S->dt[h >> 1];
        double ad = (double)argf;
        double kq2 = rint(ad * 0.15915494309189535);
        double r   = fma(-kq2, 6.283185307179586, ad);
        S->pe[i][h] = (h & 1) ? cosf((float)r) : sinf((float)r);
    }
    {   // packed triangular softmax table
        int w = tid >> 5;
        for (int c = w + 1; c < NROWS; c += 32) {
            float v0 = (lane      < c) ? S->pos[lane]      : -INFINITY;
            float v1 = (lane + 32 < c) ? S->pos[lane + 32] : -INFINITY;
            float m = fmaxf(v0, v1);
            #pragma unroll
            for (int off = 16; off > 0; off >>= 1)
                m = fmaxf(m, __shfl_xor_sync(0xffffffffu, m, off));
            float u0 = (lane      < c) ? expf(v0 - m) : 0.0f;
            float u1 = (lane + 32 < c) ? expf(v1 - m) : 0.0f;
            float s = u0 + u1;
            #pragma unroll
            for (int off = 16; off > 0; off >>= 1)
                s += __shfl_xor_sync(0xffffffffu, s, off);
            int base = c * (c - 1) / 2;
            if (lane      < c) S->wts[base + lane]      = u0 / s;
            if (lane + 32 < c) S->wts[base + lane + 32] = u1 / s;
        }
    }
    __syncthreads();

    const int g   = tid >> 8;
    const int tc  = tid & 255;
    const int hp  = tc >> 4;
    const int kq  = tc & 15;
    const int w2  = tc >> 5;

    // ---------------- prompt (R7-proven structure) ----------------
    if (tid < HDIM) e_vec[tid] = 1.0f / 64.0f;
    __syncthreads();

    for (int i = 0; i < L; ++i) {
        int edge = SE[i];
        float4 wvp[4];
        if (tid < 256) {
            const float4* Wb = (const float4*)(W + (size_t)edge * (HDIM * HDIM));
            #pragma unroll
            for (int r = 0; r < 4; ++r) wvp[r] = Wb[(hp * 4 + r) * 16 + kq];
        }
        float bias_p = 0.0f;
        if (tid < 64) bias_p = Bb[(size_t)edge * HDIM + tid];

        if (i > 0) {
            int base = i * (i - 1) / 2;
            if (tid >= 512) {
                int p = (tid >> 6) - 8, k = tid & 63;
                float acc = 0.0f;
                for (int j = p; j < i; j += 8)
                    acc = fmaf(S->wts[base + j], S->cache[j][k], acc);
                S->red_s[p][k] = acc;
            }
            __syncthreads();
            if (tid < HDIM) {
                float a = 0.0f;
                #pragma unroll
                for (int q = 0; q < 8; ++q) a += S->red_s[q][tid];
                e_vec[tid] = a;
            }
            __syncthreads();
        }
        if (tid < 256) {
            float4 a4 = make_float4(0.f, 0.f, 0.f, 0.f);
            #pragma unroll
            for (int r = 0; r < 4; ++r) {
                float ev = e_vec[hp * 4 + r];
                a4.x = fmaf(ev, wvp[r].x, a4.x); a4.y = fmaf(ev, wvp[r].y, a4.y);
                a4.z = fmaf(ev, wvp[r].z, a4.z); a4.w = fmaf(ev, wvp[r].w, a4.w);
            }
            a4.x += __shfl_xor_sync(0xffffffffu, a4.x, 16);
            a4.y += __shfl_xor_sync(0xffffffffu, a4.y, 16);
            a4.z += __shfl_xor_sync(0xffffffffu, a4.z, 16);
            a4.w += __shfl_xor_sync(0xffffffffu, a4.w, 16);
            if ((tc & 16) == 0)
                *(float4*)&S->red_f[0][w2][kq * 4] = a4;
        }
        __syncthreads();
        if (tid < HDIM) {
            float v = 0.0f;
            #pragma unroll
            for (int q = 0; q < 8; ++q) v += S->red_f[0][q][tid];
            v += bias_p + S->pe[i][tid];
            S->cache[i][tid] = gelu_exact(v);
        }
        __syncthreads();
    }

    // ---------------- generation priming ----------------
    if (tid == 0) S->x0 = (X0P != nullptr) ? X0P[0] : 7;
    __syncthreads();
    const int x0v = S->x0;

    int nn_reg = 0, nn_next = 0;
    if (tid < 32) {
        nn_reg = NN[(size_t)x0v * CNEI + tid];
        #pragma unroll
        for (int c = 0; c < 4; ++c)
            S->ne_br[tid][c] = NE[(size_t)nn_reg * CNEI + myrank * 4 + c];
    }
    if (tid < 4) S->edge0[tid] = NE[(size_t)x0v * CNEI + myrank * 4 + tid];
    __syncthreads();

    float4 wv[4];
    {
        const float4* Wb = (const float4*)(W + (size_t)S->edge0[g] * (HDIM * HDIM));
        #pragma unroll
        for (int r = 0; r < 4; ++r) wv[r] = Wb[(hp * 4 + r) * 16 + kq];
    }
    float bias_r = 0.0f;
    if (tid < 256) bias_r = Bb[(size_t)S->edge0[tid >> 6] * HDIM + (tid & 63)];

    float e_r[4] = {0.f, 0.f, 0.f, 0.f};
    if (T > 0) {   // e for curr = L -> registers
        int base = L * (L - 1) / 2;
        if (tid >= 512) {
            int p = (tid >> 6) - 8, k = tid & 63;
            float acc = 0.0f;
            for (int j = p; j < L; j += 8)
                acc = fmaf(S->wts[base + j], S->cache[j][k], acc);
            S->red_s[p][k] = acc;
        }
        __syncthreads();
        {
            float4 acc = make_float4(0.f, 0.f, 0.f, 0.f);
            #pragma unroll
            for (int q = 0; q < 8; ++q) {
                float4 rq = *(const float4*)&S->red_s[q][hp * 4];
                acc.x += rq.x; acc.y += rq.y; acc.z += rq.z; acc.w += rq.w;
            }
            e_r[0] = acc.x; e_r[1] = acc.y; e_r[2] = acc.z; e_r[3] = acc.w;
        }
    }
    cluster_sync_all();
    __syncthreads();

    // ---------------- generation loop ----------------
    for (int t = 0; t < T; ++t) {
        const int curr = L + t;
        const int cb   = t & 1;
        const uint32_t mb = cb ? mbar_a1 : mbar_a0;

        // 1) matvec partials
        {
            float4 a4 = make_float4(0.f, 0.f, 0.f, 0.f);
            #pragma unroll
            for (int r = 0; r < 4; ++r) {
                float ev = e_r[r];
                a4.x = fmaf(ev, wv[r].x, a4.x); a4.y = fmaf(ev, wv[r].y, a4.y);
                a4.z = fmaf(ev, wv[r].z, a4.z); a4.w = fmaf(ev, wv[r].w, a4.w);
            }
            a4.x += __shfl_xor_sync(0xffffffffu, a4.x, 16);
            a4.y += __shfl_xor_sync(0xffffffffu, a4.y, 16);
            a4.z += __shfl_xor_sync(0xffffffffu, a4.z, 16);
            a4.w += __shfl_xor_sync(0xffffffffu, a4.w, 16);
            if ((tc & 16) == 0)
                *(float4*)&S->red_f[g][w2][kq * 4] = a4;
        }
        __syncthreads();   // bar1

        // 2) combine+gelu into local push block | NE gathers | pooled partials
        if (tid < 256) {
            if (tid < 32 && t > 0) {
                nn_reg = nn_next;
                int e0 = NE[(size_t)nn_reg * CNEI + myrank * 4 + 0];
                int e1 = NE[(size_t)nn_reg * CNEI + myrank * 4 + 1];
                int e2 = NE[(size_t)nn_reg * CNEI + myrank * 4 + 2];
                int e3 = NE[(size_t)nn_reg * CNEI + myrank * 4 + 3];
                S->ne_br[lane][0] = e0; S->ne_br[lane][1] = e1;
                S->ne_br[lane][2] = e2; S->ne_br[lane][3] = e3;
            }
            int cand = tid >> 6, kk = tid & 63;
            float v = 0.0f;
            #pragma unroll
            for (int q = 0; q < 8; ++q) v += S->red_f[cand][q][kk];
            v += bias_r + S->pe[t][kk];
            float ge = gelu_exact(v);
            S->rx[cb][myrank].vec[cand][kk] = ge;
            float sq = ge * ge;
            #pragma unroll
            for (int off = 16; off > 0; off >>= 1)
                sq += __shfl_xor_sync(0xffffffffu, sq, off);
            if (lane == 0) S->rx[cb][myrank].en[tid >> 5] = sq;
        } else if (tid >= 512 && t + 1 < T) {
            int p = (tid >> 6) - 8, k = tid & 63;
            int base1 = (curr + 1) * curr / 2;
            float acc = 0.0f;
            for (int j = p; j < curr; j += 8)
                acc = fmaf(S->wts[base1 + j], S->cache[j][k], acc);
            S->red_s[p][k] = acc;
        }
        __syncthreads();   // bar2

        // 3) one thread: fence + expect + 7 bulk pushes (single exchange)
        if (tid == 0) {
            asm volatile("fence.proxy.async.shared::cta;" ::: "memory");
            mbar_arrive_expect(mb, EXPECT_TX);
            uint32_t src = (uint32_t)__cvta_generic_to_shared(&S->rx[cb][myrank]);
            #pragma unroll
            for (int r = 0; r < NBLK; ++r) {
                if ((uint32_t)r == myrank) continue;
                bulk_s2s(mapa_u32(src, (uint32_t)r), src, PUSH_BYTES, mapa_u32(mb, (uint32_t)r));
            }
        }

        // 4) wait for all 7 peer blocks
        mbar_wait(mb, (uint32_t)((t >> 1) & 1));

        // 5) per-warp redundant argmax over local energies
        int bi;
        {
            int rr = lane >> 2, cl = lane & 3;
            float2 eh = *(const float2*)&S->rx[cb][rr].en[cl * 2];
            float best = eh.x + eh.y;
            bi = lane;
            #pragma unroll
            for (int off = 16; off > 0; off >>= 1) {
                float bo = __shfl_xor_sync(0xffffffffu, best, off);
                int   io = __shfl_xor_sync(0xffffffffu, bi, off);
                if (bo > best || (bo == best && io < bi)) { best = bo; bi = io; }
            }
        }
        if (tid < 32) {
            int y = __shfl_sync(0xffffffffu, nn_reg, bi);
            if (lane == 0) S->tok[t] = y;
            nn_next = NN[(size_t)y * CNEI + lane];
        }

        // 6) next-step weight/bias loads + winner (local) + register e update
        {
            int edge_g = S->ne_br[bi][g];
            const float4* Wb = (const float4*)(W + (size_t)edge_g * (HDIM * HDIM));
            #pragma unroll
            for (int r = 0; r < 4; ++r) wv[r] = Wb[(hp * 4 + r) * 16 + kq];
        }
        if (tid < 256)
            bias_r = Bb[(size_t)S->ne_br[bi][tid >> 6] * HDIM + (tid & 63)];

        const float* winp = &S->rx[cb][bi >> 2].vec[bi & 3][0];
        if (tid < 64) S->cache[curr][tid] = winp[tid];
        if (t + 1 < T) {
            float wcur = S->wts[(curr + 1) * curr / 2 + curr];
            float4 acc = make_float4(0.f, 0.f, 0.f, 0.f);
            #pragma unroll
            for (int q = 0; q < 8; ++q) {
                float4 rq = *(const float4*)&S->red_s[q][hp * 4];
                acc.x += rq.x; acc.y += rq.y; acc.z += rq.z; acc.w += rq.w;
            }
            float4 wn = *(const float4*)&winp[hp * 4];
            e_r[0] = fmaf(wcur, wn.x, acc.x);
            e_r[1] = fmaf(wcur, wn.y, acc.y);
            e_r[2] = fmaf(wcur, wn.z, acc.z);
            e_r[3] = fmaf(wcur, wn.w, acc.w);
        }
        // no bar4: all hazards ordered by bar1/bar2 of the next iteration
    }

    // protect in-flight outgoing bulk reads of our smem before exit
    cluster_sync_all();
    __syncthreads();

    // ---------------- output (CTA 0) ----------------
    if (blockIdx.x == 0) {
        int ncache = (L + T) * HDIM;
        for (int i = tid; i < out_size; i += NTHR) {
            float v;
            if (i < ncache) v = S->cache[i >> 6][i & 63];
            else {
                int tt = i - ncache;
                v = (tt < T) ? (float)S->tok[tt] : 0.0f;
            }
            out[i] = v;
        }
    }
}

extern "C" void kernel_launch(void* const* d_in, const int* in_sizes, int n_in,
                              void* d_out, int out_size) {
    const float* W   = (const float*)d_in[0];
    const float* B   = (const float*)d_in[1];
    const float* POS = (const float*)d_in[2];
    const int*   SE  = (const int*)d_in[3];
    const int*   NE  = (const int*)d_in[4];
    const int*   NN  = (const int*)d_in[5];
    const int*   X0  = (n_in > 6) ? (const int*)d_in[6] : nullptr;
    const int*   MNT = (n_in > 7) ? (const int*)d_in[7] : nullptr;
    int L = in_sizes[3];

    cudaFuncSetAttribute(bralm_kernel,
                         cudaFuncAttributeMaxDynamicSharedMemorySize,
                         (int)sizeof(Smem));
    bralm_kernel<<<NBLK, NTHR, sizeof(Smem)>>>(W, B, POS, SE, NE, NN, X0, MNT,
                                               (float*)d_out, out_size, L);
}

// round 10
// speedup vs baseline: 1.1490x; 1.0607x over previous
#include <cuda_runtime.h>
#include <cstdint>
#include <stdint.h>
#include <math.h>

#define HDIM   64
#define CNEI   32
#define NBLK   8
#define NTHR   1024
#define TROWS  32
#define NROWS  48
#define WPACK  1128

#define EN_BYTES   32
#define EN_EXPECT  ((NBLK - 1) * EN_BYTES)
#define VEC_BYTES  1024
#define VEC_EXPECT ((NBLK - 1) * VEC_BYTES)

struct __align__(16) Smem {
    float vec_rx[2][NBLK][4][HDIM];   // 16 KB
    float en_rx[2][NBLK][8];          // 512 B
    float pe[TROWS][HDIM];            // 8 KB
    float cache[NROWS][HDIM];         // 12 KB
    float wts[WPACK];                 // 4.5 KB
    float red_s[8][HDIM];             // 2 KB
    float red_f[4][8][HDIM];          // 8 KB
    float pos[64];
    float dt[32];
    int   tok[TROWS];
    int   ne_br[CNEI][4];
    int   edge0[4];
    int   x0;
    unsigned long long mbarE[2], mbarV[2];
};

__device__ __forceinline__ float gelu_exact(float v) {
    return 0.5f * v * (1.0f + erff(v * 0.70710678118654752440f));
}
__device__ __forceinline__ uint32_t mapa_u32(uint32_t addr, uint32_t rank) {
    uint32_t d;
    asm("mapa.shared::cluster.u32 %0, %1, %2;" : "=r"(d) : "r"(addr), "r"(rank));
    return d;
}
__device__ __forceinline__ void cluster_sync_all() {
    asm volatile("barrier.cluster.arrive.aligned;" ::: "memory");
    asm volatile("barrier.cluster.wait.aligned;"   ::: "memory");
}
__device__ __forceinline__ void mbar_init(uint32_t a, uint32_t cnt) {
    asm volatile("mbarrier.init.shared.b64 [%0], %1;" :: "r"(a), "r"(cnt) : "memory");
}
__device__ __forceinline__ void mbar_arrive_expect(uint32_t a, uint32_t tx) {
    asm volatile("mbarrier.arrive.expect_tx.shared.b64 _, [%0], %1;" :: "r"(a), "r"(tx) : "memory");
}
__device__ __forceinline__ void mbar_wait(uint32_t a, uint32_t parity) {
    uint32_t done;
    asm volatile(
        "{\n\t.reg .pred p;\n\t"
        "mbarrier.try_wait.parity.acquire.cta.shared::cta.b64 p, [%1], %2;\n\t"
        "selp.b32 %0, 1, 0, p;\n\t}"
        : "=r"(done) : "r"(a), "r"(parity) : "memory");
    if (!done) {
        asm volatile(
            "{\n\t.reg .pred P1;\n\t"
            "WAIT_LOOP_%=:\n\t"
            "mbarrier.try_wait.parity.acquire.cta.shared::cta.b64 P1, [%0], %1, 0x989680;\n\t"
            "@P1 bra.uni WAIT_DONE_%=;\n\t"
            "bra.uni WAIT_LOOP_%=;\n\t"
            "WAIT_DONE_%=:\n\t}"
            :: "r"(a), "r"(parity) : "memory");
    }
}
__device__ __forceinline__ void bulk_s2s(uint32_t dst, uint32_t src, uint32_t bytes, uint32_t rmbar) {
    asm volatile(
        "cp.async.bulk.shared::cluster.shared::cta.mbarrier::complete_tx::bytes [%0], [%1], %2, [%3];"
        :: "r"(dst), "r"(src), "r"(bytes), "r"(rmbar) : "memory");
}

__global__ __launch_bounds__(NTHR, 1) __cluster_dims__(NBLK, 1, 1)
void bralm_kernel(const float* __restrict__ W,
                  const float* __restrict__ Bb,
                  const float* __restrict__ POS,
                  const int*   __restrict__ SE,
                  const int*   __restrict__ NE,
                  const int*   __restrict__ NN,
                  const int*   __restrict__ X0P,
                  const int*   __restrict__ MNTP,
                  float* __restrict__ out,
                  int out_size, int L)
{
    extern __shared__ __align__(16) char smem_raw[];
    Smem* S = (Smem*)smem_raw;
    __shared__ float e_vec[HDIM];

    const int tid  = threadIdx.x;
    const int lane = tid & 31;
    uint32_t myrank;
    asm("mov.u32 %0, %%cluster_ctarank;" : "=r"(myrank));

    const uint32_t mbE_a[2] = { (uint32_t)__cvta_generic_to_shared(&S->mbarE[0]),
                                (uint32_t)__cvta_generic_to_shared(&S->mbarE[1]) };
    const uint32_t mbV_a[2] = { (uint32_t)__cvta_generic_to_shared(&S->mbarV[0]),
                                (uint32_t)__cvta_generic_to_shared(&S->mbarV[1]) };

    int T = (MNTP != nullptr) ? MNTP[0] : 32;
    if (T < 0) T = 0;
    if (L + T > NROWS) T = NROWS - L;
    if (T > TROWS)     T = TROWS;

    // ---------------- init ----------------
    if (tid == 0) {
        mbar_init(mbE_a[0], 1); mbar_init(mbE_a[1], 1);
        mbar_init(mbV_a[0], 1); mbar_init(mbV_a[1], 1);
    }
    if (tid < HDIM / 2)
        S->dt[tid] = (float)pow(10000.0, (double)(2 * tid) / 64.0);
    for (int i = tid; i < NROWS * HDIM; i += NTHR)
        S->cache[i >> 6][i & 63] = 0.0f;
    if (tid < 64) S->pos[tid] = POS[tid];
    __syncthreads();

    for (int idx = tid; idx < TROWS * HDIM; idx += NTHR) {
        int i = idx >> 6, h = idx & 63;
        float argf = (float)i * S->dt[h >> 1];
        double ad = (double)argf;
        double kq2 = rint(ad * 0.15915494309189535);
        double r   = fma(-kq2, 6.283185307179586, ad);
        S->pe[i][h] = (h & 1) ? cosf((float)r) : sinf((float)r);
    }
    {   // packed triangular softmax table
        int w = tid >> 5;
        for (int c = w + 1; c < NROWS; c += 32) {
            float v0 = (lane      < c) ? S->pos[lane]      : -INFINITY;
            float v1 = (lane + 32 < c) ? S->pos[lane + 32] : -INFINITY;
            float m = fmaxf(v0, v1);
            #pragma unroll
            for (int off = 16; off > 0; off >>= 1)
                m = fmaxf(m, __shfl_xor_sync(0xffffffffu, m, off));
            float u0 = (lane      < c) ? expf(v0 - m) : 0.0f;
            float u1 = (lane + 32 < c) ? expf(v1 - m) : 0.0f;
            float s = u0 + u1;
            #pragma unroll
            for (int off = 16; off > 0; off >>= 1)
                s += __shfl_xor_sync(0xffffffffu, s, off);
            int base = c * (c - 1) / 2;
            if (lane      < c) S->wts[base + lane]      = u0 / s;
            if (lane + 32 < c) S->wts[base + lane + 32] = u1 / s;
        }
    }
    __syncthreads();

    const int g   = tid >> 8;
    const int tc  = tid & 255;
    const int hp  = tc >> 4;
    const int kq  = tc & 15;
    const int w2  = tc >> 5;

    // ---------------- prompt (R7-proven structure) ----------------
    if (tid < HDIM) e_vec[tid] = 1.0f / 64.0f;
    __syncthreads();

    for (int i = 0; i < L; ++i) {
        int edge = SE[i];
        float4 wvp[4];
        if (tid < 256) {
            const float4* Wb = (const float4*)(W + (size_t)edge * (HDIM * HDIM));
            #pragma unroll
            for (int r = 0; r < 4; ++r) wvp[r] = Wb[(hp * 4 + r) * 16 + kq];
        }
        float bias_p = 0.0f;
        if (tid < 64) bias_p = Bb[(size_t)edge * HDIM + tid];

        if (i > 0) {
            int base = i * (i - 1) / 2;
            if (tid >= 512) {
                int p = (tid >> 6) - 8, k = tid & 63;
                float acc = 0.0f;
                for (int j = p; j < i; j += 8)
                    acc = fmaf(S->wts[base + j], S->cache[j][k], acc);
                S->red_s[p][k] = acc;
            }
            __syncthreads();
            if (tid < HDIM) {
                float a = 0.0f;
                #pragma unroll
                for (int q = 0; q < 8; ++q) a += S->red_s[q][tid];
                e_vec[tid] = a;
            }
            __syncthreads();
        }
        if (tid < 256) {
            float4 a4 = make_float4(0.f, 0.f, 0.f, 0.f);
            #pragma unroll
            for (int r = 0; r < 4; ++r) {
                float ev = e_vec[hp * 4 + r];
                a4.x = fmaf(ev, wvp[r].x, a4.x); a4.y = fmaf(ev, wvp[r].y, a4.y);
                a4.z = fmaf(ev, wvp[r].z, a4.z); a4.w = fmaf(ev, wvp[r].w, a4.w);
            }
            a4.x += __shfl_xor_sync(0xffffffffu, a4.x, 16);
            a4.y += __shfl_xor_sync(0xffffffffu, a4.y, 16);
            a4.z += __shfl_xor_sync(0xffffffffu, a4.z, 16);
            a4.w += __shfl_xor_sync(0xffffffffu, a4.w, 16);
            if ((tc & 16) == 0)
                *(float4*)&S->red_f[0][w2][kq * 4] = a4;
        }
        __syncthreads();
        if (tid < HDIM) {
            float v = 0.0f;
            #pragma unroll
            for (int q = 0; q < 8; ++q) v += S->red_f[0][q][tid];
            v += bias_p + S->pe[i][tid];
            S->cache[i][tid] = gelu_exact(v);
        }
        __syncthreads();
    }

    // ---------------- generation priming ----------------
    if (tid == 0) S->x0 = (X0P != nullptr) ? X0P[0] : 7;
    __syncthreads();
    const int x0v = S->x0;

    int nn_reg = 0, nn_next = 0;
    if (tid < 32) {
        nn_reg = NN[(size_t)x0v * CNEI + tid];
        #pragma unroll
        for (int c = 0; c < 4; ++c)
            S->ne_br[tid][c] = NE[(size_t)nn_reg * CNEI + myrank * 4 + c];
    }
    if (tid < 4) S->edge0[tid] = NE[(size_t)x0v * CNEI + myrank * 4 + tid];
    __syncthreads();

    float4 wv[4];
    {
        const float4* Wb = (const float4*)(W + (size_t)S->edge0[g] * (HDIM * HDIM));
        #pragma unroll
        for (int r = 0; r < 4; ++r) wv[r] = Wb[(hp * 4 + r) * 16 + kq];
    }
    float bias_r = 0.0f;
    if (tid < 256) bias_r = Bb[(size_t)S->edge0[tid >> 6] * HDIM + (tid & 63)];

    if (T > 0) {   // e for curr = L
        int base = L * (L - 1) / 2;
        if (tid >= 512) {
            int p = (tid >> 6) - 8, k = tid & 63;
            float acc = 0.0f;
            for (int j = p; j < L; j += 8)
                acc = fmaf(S->wts[base + j], S->cache[j][k], acc);
            S->red_s[p][k] = acc;
        }
        __syncthreads();
        if (tid < HDIM) {
            float a = 0.0f;
            #pragma unroll
            for (int q = 0; q < 8; ++q) a += S->red_s[q][tid];
            e_vec[tid] = a;
        }
    }
    cluster_sync_all();
    __syncthreads();

    // ---------------- generation loop ----------------
    for (int t = 0; t < T; ++t) {
        const int curr = L + t;
        const int cb   = t & 1;
        const uint32_t par = (uint32_t)((t >> 1) & 1);

        // 1) matvec partials
        {
            float4 a4 = make_float4(0.f, 0.f, 0.f, 0.f);
            #pragma unroll
            for (int r = 0; r < 4; ++r) {
                float ev = e_vec[hp * 4 + r];
                a4.x = fmaf(ev, wv[r].x, a4.x); a4.y = fmaf(ev, wv[r].y, a4.y);
                a4.z = fmaf(ev, wv[r].z, a4.z); a4.w = fmaf(ev, wv[r].w, a4.w);
            }
            a4.x += __shfl_xor_sync(0xffffffffu, a4.x, 16);
            a4.y += __shfl_xor_sync(0xffffffffu, a4.y, 16);
            a4.z += __shfl_xor_sync(0xffffffffu, a4.z, 16);
            a4.w += __shfl_xor_sync(0xffffffffu, a4.w, 16);
            if ((tc & 16) == 0)
                *(float4*)&S->red_f[g][w2][kq * 4] = a4;
        }
        __syncthreads();   // bar1

        // 2) combine+gelu into local slots | NE gathers | pooled partials
        if (tid < 256) {
            if (tid < 32 && t > 0) {
                nn_reg = nn_next;
                int e0 = NE[(size_t)nn_reg * CNEI + myrank * 4 + 0];
                int e1 = NE[(size_t)nn_reg * CNEI + myrank * 4 + 1];
                int e2 = NE[(size_t)nn_reg * CNEI + myrank * 4 + 2];
                int e3 = NE[(size_t)nn_reg * CNEI + myrank * 4 + 3];
                S->ne_br[lane][0] = e0; S->ne_br[lane][1] = e1;
                S->ne_br[lane][2] = e2; S->ne_br[lane][3] = e3;
            }
            int cand = tid >> 6, kk = tid & 63;
            float v = 0.0f;
            #pragma unroll
            for (int q = 0; q < 8; ++q) v += S->red_f[cand][q][kk];
            v += bias_r + S->pe[t][kk];
            float ge = gelu_exact(v);
            S->vec_rx[cb][myrank][cand][kk] = ge;
            float sq = ge * ge;
            #pragma unroll
            for (int off = 16; off > 0; off >>= 1)
                sq += __shfl_xor_sync(0xffffffffu, sq, off);
            if (lane == 0) S->en_rx[cb][myrank][tid >> 5] = sq;
        } else if (tid >= 512 && t + 1 < T) {
            int p = (tid >> 6) - 8, k = tid & 63;
            int base1 = (curr + 1) * curr / 2;
            float acc = 0.0f;
            for (int j = p; j < curr; j += 8)
                acc = fmaf(S->wts[base1 + j], S->cache[j][k], acc);
            S->red_s[p][k] = acc;
        }
        __syncthreads();   // bar2

        // 3) eager split push: energies (32 B) AND vectors (1024 B), both in flight now
        if (tid == 0) {
            asm volatile("fence.proxy.async.shared::cta;" ::: "memory");
            mbar_arrive_expect(mbE_a[cb], EN_EXPECT);
            mbar_arrive_expect(mbV_a[cb], VEC_EXPECT);
            uint32_t esrc = (uint32_t)__cvta_generic_to_shared(&S->en_rx[cb][myrank][0]);
            uint32_t vsrc = (uint32_t)__cvta_generic_to_shared(&S->vec_rx[cb][myrank][0][0]);
            #pragma unroll
            for (int r = 0; r < NBLK; ++r) {
                if ((uint32_t)r == myrank) continue;
                bulk_s2s(mapa_u32(esrc, (uint32_t)r), esrc, EN_BYTES, mapa_u32(mbE_a[cb], (uint32_t)r));
            }
            #pragma unroll
            for (int r = 0; r < NBLK; ++r) {
                if ((uint32_t)r == myrank) continue;
                bulk_s2s(mapa_u32(vsrc, (uint32_t)r), vsrc, VEC_BYTES, mapa_u32(mbV_a[cb], (uint32_t)r));
            }
        }

        // 4) wait energies only (224 B ingress)
        mbar_wait(mbE_a[cb], par);

        // 5) per-warp redundant argmax over the 32 sum-of-squares
        int bi;
        {
            int rr = lane >> 2, cl = lane & 3;
            float2 eh = *(const float2*)&S->en_rx[cb][rr][cl * 2];
            float best = eh.x + eh.y;
            bi = lane;
            #pragma unroll
            for (int off = 16; off > 0; off >>= 1) {
                float bo = __shfl_xor_sync(0xffffffffu, best, off);
                int   io = __shfl_xor_sync(0xffffffffu, bi, off);
                if (bo > best || (bo == best && io < bi)) { best = bo; bi = io; }
            }
        }
        if (tid < 32) {
            int y = __shfl_sync(0xffffffffu, nn_reg, bi);
            if (lane == 0) S->tok[t] = y;
            nn_next = NN[(size_t)y * CNEI + lane];
        }

        // 6) next-step weight/bias loads (overlap vector ingress)
        {
            int edge_g = S->ne_br[bi][g];
            const float4* Wb = (const float4*)(W + (size_t)edge_g * (HDIM * HDIM));
            #pragma unroll
            for (int r = 0; r < 4; ++r) wv[r] = Wb[(hp * 4 + r) * 16 + kq];
        }
        if (tid < 256)
            bias_r = Bb[(size_t)S->ne_br[bi][tid >> 6] * HDIM + (tid & 63)];

        // 7) wait vectors, then 64-thread cache/e update (R7 style)
        mbar_wait(mbV_a[cb], par);
        if (tid < HDIM) {
            float win = S->vec_rx[cb][bi >> 2][bi & 3][tid];
            S->cache[curr][tid] = win;
            if (t + 1 < T) {
                int base1 = (curr + 1) * curr / 2;
                float ee = 0.0f;
                #pragma unroll
                for (int q = 0; q < 8; ++q) ee += S->red_s[q][tid];
                e_vec[tid] = fmaf(S->wts[base1 + curr], win, ee);
            }
        }
        __syncthreads();   // bar4
    }

    // drain outgoing bulk reads before exit
    cluster_sync_all();
    __syncthreads();

    // ---------------- output (CTA 0) ----------------
    if (blockIdx.x == 0) {
        int ncache = (L + T) * HDIM;
        for (int i = tid; i < out_size; i += NTHR) {
            float v;
            if (i < ncache) v = S->cache[i >> 6][i & 63];
            else {
                int tt = i - ncache;
                v = (tt < T) ? (float)S->tok[tt] : 0.0f;
            }
            out[i] = v;
        }
    }
}

extern "C" void kernel_launch(void* const* d_in, const int* in_sizes, int n_in,
                              void* d_out, int out_size) {
    const float* W   = (const float*)d_in[0];
    const float* B   = (const float*)d_in[1];
    const float* POS = (const float*)d_in[2];
    const int*   SE  = (const int*)d_in[3];
    const int*   NE  = (const int*)d_in[4];
    const int*   NN  = (const int*)d_in[5];
    const int*   X0  = (n_in > 6) ? (const int*)d_in[6] : nullptr;
    const int*   MNT = (n_in > 7) ? (const int*)d_in[7] : nullptr;
    int L = in_sizes[3];

    cudaFuncSetAttribute(bralm_kernel,
                         cudaFuncAttributeMaxDynamicSharedMemorySize,
                         (int)sizeof(Smem));
    bralm_kernel<<<NBLK, NTHR, sizeof(Smem)>>>(W, B, POS, SE, NE, NN, X0, MNT,
                                               (float*)d_out, out_size, L);
}